// round 8
// baseline (speedup 1.0000x reference)
#include <cuda_runtime.h>
#include <cstdint>

#define IN_F   4096
#define OUT_F  4096
#define PACKED (IN_F / 2)
#define NBLK   (IN_F / 64)

#define BM 128
#define BN 256
#define BK 32
#define NKT (IN_F / BK)             // 128 k-tiles
#define TILE_FLOATS 4096            // one 128x32 fragment-ordered block = 16 KB
#define STAGE_BYTES 49152           // A (16KB) + B part0 (16KB) + B part1 (16KB)
#define STAGES 4
#define SMEM_BYTES (STAGES * STAGE_BYTES)   // 196608 B -> 1 CTA/SM, 8 warps

// Fragment-ordered, tf32-pre-rounded operand scratch.
// A block (128x32): float idx = (kk*8 + mf)*128 + lane*4 + slot
//   lane = (rr&7)*4 + c, slot = (rr>>3) + 2*hi, m'=mf*16+rr, k'=kk*8+hi*4+c
// B block (128x32): float idx = (kk*16 + nf)*64 + lane*2 + hi
//   lane = (n'&7)*4 + c, n'=nf*8+(n'&7), k'=kk*8+hi*4+c
__device__ float g_At[(size_t)(8192 / BM) * NKT * TILE_FLOATS];   // 134 MB
__device__ float g_Bt[(size_t)(OUT_F / 128) * NKT * TILE_FLOATS]; //  67 MB

// ---------------------------------------------------------------------------
// Pre-pass 1: dequantize 4-bit codes -> tf32 bits -> fragment-ordered g_Bt.
// ---------------------------------------------------------------------------
__global__ void dequant_kernel(const int* __restrict__ wp,
                               const float* __restrict__ centroids,
                               const float* __restrict__ scales) {
    __shared__ float cent[16];
    if (threadIdx.x < 16) cent[threadIdx.x] = centroids[threadIdx.x];
    __syncthreads();

    int idx = blockIdx.x * blockDim.x + threadIdx.x;
    if (idx >= OUT_F * PACKED) return;
    int o = idx >> 11;              // / 2048
    int j = idx & (PACKED - 1);

    int v = wp[idx] & 255;
    float s = scales[o * NBLK + (j >> 5)];
    float w0 = cent[(v >> 4) & 15] * s;   // element k0 = 2j
    float w1 = cent[v & 15] * s;          // element k0+1

    uint32_t t0, t1;
    asm("cvt.rna.tf32.f32 %0, %1;" : "=r"(t0) : "f"(w0));
    asm("cvt.rna.tf32.f32 %0, %1;" : "=r"(t1) : "f"(w1));

    int k0 = 2 * j;
    int ntile = o >> 7;             // 128-row block index
    int np = o & 127;
    int kt = k0 >> 5;
    int kp = k0 & 31;
    int kk = kp >> 3;
    int q  = kp & 7;
    int c  = q & 3;                 // even (0 or 2)
    int hi = q >> 2;
    int nf = np >> 3;
    int lane = (np & 7) * 4 + c;

    float* tile = g_Bt + (size_t)ntile * (NKT * TILE_FLOATS) + (size_t)kt * TILE_FLOATS;
    int f0 = (kk * 16 + nf) * 64 + lane * 2 + hi;
    tile[f0]     = __uint_as_float(t0);
    tile[f0 + 2] = __uint_as_float(t1);   // c+1 -> lane+1 -> +2 floats
}

// ---------------------------------------------------------------------------
// Pre-pass 2: tf32-round X -> fragment-ordered g_At.
// ---------------------------------------------------------------------------
__global__ void retile_x_kernel(const float* __restrict__ X, int M) {
    int t = blockIdx.x * blockDim.x + threadIdx.x;
    if (t >= M * (IN_F / 4)) return;
    int e = t * 4;
    int m = e >> 12;
    int i = e & (IN_F - 1);

    float4 v = *reinterpret_cast<const float4*>(X + (size_t)m * IN_F + i);
    uint32_t t0, t1, t2, t3;
    asm("cvt.rna.tf32.f32 %0, %1;" : "=r"(t0) : "f"(v.x));
    asm("cvt.rna.tf32.f32 %0, %1;" : "=r"(t1) : "f"(v.y));
    asm("cvt.rna.tf32.f32 %0, %1;" : "=r"(t2) : "f"(v.z));
    asm("cvt.rna.tf32.f32 %0, %1;" : "=r"(t3) : "f"(v.w));

    int mtile = m >> 7;
    int mp = m & 127;
    int mf = mp >> 4;
    int rr = mp & 15;
    int kt = i >> 5;
    int kp = i & 31;
    int kk = kp >> 3;
    int hi = (kp & 7) >> 2;
    int lane0 = (rr & 7) * 4;
    int slot = ((rr >> 3) & 1) + 2 * hi;

    float* tile = g_At + (size_t)mtile * (NKT * TILE_FLOATS) + (size_t)kt * TILE_FLOATS;
    int base = (kk * 8 + mf) * 128 + lane0 * 4 + slot;
    tile[base]      = __uint_as_float(t0);
    tile[base + 4]  = __uint_as_float(t1);
    tile[base + 8]  = __uint_as_float(t2);
    tile[base + 12] = __uint_as_float(t3);
}

// ---------------------------------------------------------------------------
// GEMM: 128x256x32 CTA tile, 8 warps (2x4, warp tile 64x64), mma.sync tf32.
// Fragment-ordered SMEM, 4-stage cp.async pipeline, wait -> barrier -> load
// ordering (barrier AFTER wait: cp.async groups are per-thread, so cross-
// thread visibility of a tile requires a barrier after wait_group).
// ---------------------------------------------------------------------------
__device__ __forceinline__ void mma_tf32(float* c, const uint32_t* a, const uint32_t* b) {
    asm volatile(
        "mma.sync.aligned.m16n8k8.row.col.f32.tf32.tf32.f32 "
        "{%0,%1,%2,%3}, {%4,%5,%6,%7}, {%8,%9}, {%0,%1,%2,%3};\n"
        : "+f"(c[0]), "+f"(c[1]), "+f"(c[2]), "+f"(c[3])
        : "r"(a[0]), "r"(a[1]), "r"(a[2]), "r"(a[3]),
          "r"(b[0]), "r"(b[1]));
}

__device__ __forceinline__ void load_stage(uint32_t sbase, const float* Asrc,
                                           const float* B0src, const float* B1src,
                                           int kt, int buf, int tid) {
    uint32_t d = sbase + (uint32_t)buf * STAGE_BYTES + (uint32_t)tid * 16;
    const float* pa = Asrc + (size_t)kt * TILE_FLOATS + tid * 4;
    const float* p0 = B0src + (size_t)kt * TILE_FLOATS + tid * 4;
    const float* p1 = B1src + (size_t)kt * TILE_FLOATS + tid * 4;
#pragma unroll
    for (int i = 0; i < 4; i++) {
        asm volatile("cp.async.cg.shared.global [%0], [%1], 16;\n"
                     :: "r"(d + i * 4096), "l"(pa + i * 1024));
        asm volatile("cp.async.cg.shared.global [%0], [%1], 16;\n"
                     :: "r"(d + 16384 + i * 4096), "l"(p0 + i * 1024));
        asm volatile("cp.async.cg.shared.global [%0], [%1], 16;\n"
                     :: "r"(d + 32768 + i * 4096), "l"(p1 + i * 1024));
    }
}

__global__ void __launch_bounds__(256, 1)
gemm_tf32_kernel(float* __restrict__ Out) {
    extern __shared__ float smem[];

    const int tid  = threadIdx.x;
    const int warp = tid >> 5;
    const int lane = tid & 31;
    const int wm = warp >> 2;              // 0..1 -> M offset wm*64
    const int wn = warp & 3;               // 0..3 -> N offset wn*64

    const float* Ag  = g_At + (size_t)blockIdx.y * (NKT * TILE_FLOATS);
    const float* Bg0 = g_Bt + (size_t)(2 * blockIdx.x)     * (NKT * TILE_FLOATS);
    const float* Bg1 = g_Bt + (size_t)(2 * blockIdx.x + 1) * (NKT * TILE_FLOATS);

    const uint32_t sbase = (uint32_t)__cvta_generic_to_shared(smem);

    float c[4][8][4];
#pragma unroll
    for (int i = 0; i < 4; i++)
#pragma unroll
        for (int j = 0; j < 8; j++)
#pragma unroll
            for (int k = 0; k < 4; k++) c[i][j][k] = 0.0f;

    // prologue: tiles 0,1,2 -> buffers 0,1,2
#pragma unroll
    for (int p = 0; p < 3; p++) {
        load_stage(sbase, Ag, Bg0, Bg1, p, p, tid);
        asm volatile("cp.async.commit_group;\n" ::: "memory");
    }

    // B fragment addressing: part = wn>>1, nf_in_part = (wn&1)*8 + nb
    const int bpart = wn >> 1;
    const int bnf0  = (wn & 1) * 8;

    for (int kt = 0; kt < NKT; kt++) {
        // my groups for tile kt complete (pending = {kt+1, kt+2})
        asm volatile("cp.async.wait_group 2;\n" ::: "memory");
        // everyone's tile-kt writes visible; buffer (kt+3)&3 no longer read
        __syncthreads();

        if (kt + 3 < NKT)
            load_stage(sbase, Ag, Bg0, Bg1, kt + 3, (kt + 3) & 3, tid);
        asm volatile("cp.async.commit_group;\n" ::: "memory");

        const float* S  = smem + (size_t)(kt & 3) * (STAGE_BYTES / 4);
        const float* A0 = S;                                     // A block
        const float* Bp = S + TILE_FLOATS + bpart * TILE_FLOATS; // this warp's B part

#pragma unroll
        for (int kk = 0; kk < 4; kk++) {
            uint32_t a[4][4];
            uint32_t b[8][2];
#pragma unroll
            for (int ma = 0; ma < 4; ma++) {
                const float4 v = *reinterpret_cast<const float4*>(
                    A0 + (kk * 8 + wm * 4 + ma) * 128 + lane * 4);
                a[ma][0] = __float_as_uint(v.x);
                a[ma][1] = __float_as_uint(v.y);
                a[ma][2] = __float_as_uint(v.z);
                a[ma][3] = __float_as_uint(v.w);
            }
#pragma unroll
            for (int nb = 0; nb < 8; nb++) {
                const float2 v = *reinterpret_cast<const float2*>(
                    Bp + (kk * 16 + bnf0 + nb) * 64 + lane * 2);
                b[nb][0] = __float_as_uint(v.x);
                b[nb][1] = __float_as_uint(v.y);
            }
#pragma unroll
            for (int ma = 0; ma < 4; ma++)
#pragma unroll
                for (int nb = 0; nb < 8; nb++)
                    mma_tf32(c[ma][nb], a[ma], b[nb]);
        }
    }

    // epilogue
    float* Og = Out + (size_t)blockIdx.y * BM * OUT_F + (size_t)blockIdx.x * BN;
#pragma unroll
    for (int ma = 0; ma < 4; ma++) {
#pragma unroll
        for (int nb = 0; nb < 8; nb++) {
            int r  = wm * 64 + ma * 16 + (lane >> 2);
            int cc = wn * 64 + nb * 8 + 2 * (lane & 3);
            *reinterpret_cast<float2*>(&Og[(size_t)r * OUT_F + cc]) =
                make_float2(c[ma][nb][0], c[ma][nb][1]);
            *reinterpret_cast<float2*>(&Og[(size_t)(r + 8) * OUT_F + cc]) =
                make_float2(c[ma][nb][2], c[ma][nb][3]);
        }
    }
}

// ---------------------------------------------------------------------------
extern "C" void kernel_launch(void* const* d_in, const int* in_sizes, int n_in,
                              void* d_out, int out_size) {
    const float* x      = (const float*)d_in[0];   // [M, 4096] fp32
    const int*   wp     = (const int*)d_in[1];     // [4096, 2048] int32 bytes
    const float* cent   = (const float*)d_in[2];   // [16]
    const float* scales = (const float*)d_in[3];   // [4096, 64]
    float* out = (float*)d_out;

    const int M = in_sizes[0] / IN_F;              // 8192

    int totalW = OUT_F * PACKED;
    dequant_kernel<<<(totalW + 255) / 256, 256>>>(wp, cent, scales);

    int totalX4 = M * (IN_F / 4);
    retile_x_kernel<<<(totalX4 + 255) / 256, 256>>>(x, M);

    cudaFuncSetAttribute(gemm_tf32_kernel,
                         cudaFuncAttributeMaxDynamicSharedMemorySize, SMEM_BYTES);
    dim3 grid(OUT_F / BN, M / BM);                 // (16, 64)
    gemm_tf32_kernel<<<grid, 256, SMEM_BYTES>>>(out);
}

// round 9
// speedup vs baseline: 1.1160x; 1.1160x over previous
#include <cuda_runtime.h>
#include <cstdint>

#define IN_F   4096
#define OUT_F  4096
#define PACKED (IN_F / 2)
#define NBLK   (IN_F / 64)

#define BM 128
#define BN 128
#define BK 32
#define NKT (IN_F / BK)             // 128 k-tiles
#define TILE_FLOATS 4096            // 128x32 floats = 16 KB (fragment-ordered)
#define STAGE_BYTES  32768          // A + B
#define STAGES 3
#define SMEM_BYTES (STAGES * STAGE_BYTES)   // 98304 B -> 2 CTA/SM

// Fragment-ordered, tf32-pre-rounded operand scratch.
// A tile (128x32): float idx = (kk*8 + mf)*128 + lane*4 + slot
//   lane = (rr&7)*4 + c, slot = (rr>>3) + 2*hi, m'=mf*16+rr, k'=kk*8+hi*4+c
// B tile (128x32): float idx = (kk*16 + nf)*64 + lane*2 + hi
//   lane = (n'&7)*4 + c, n'=nf*8+(n'&7), k'=kk*8+hi*4+c
__device__ float g_At[(size_t)(8192 / BM) * NKT * TILE_FLOATS];   // 134 MB
__device__ float g_Bt[(size_t)(OUT_F / BN) * NKT * TILE_FLOATS];  //  67 MB

// ---------------------------------------------------------------------------
// Pre-pass 1: dequantize 4-bit codes -> tf32 bits -> fragment-ordered g_Bt.
// ---------------------------------------------------------------------------
__global__ void dequant_kernel(const int* __restrict__ wp,
                               const float* __restrict__ centroids,
                               const float* __restrict__ scales) {
    __shared__ float cent[16];
    if (threadIdx.x < 16) cent[threadIdx.x] = centroids[threadIdx.x];
    __syncthreads();

    int idx = blockIdx.x * blockDim.x + threadIdx.x;
    if (idx >= OUT_F * PACKED) return;
    int o = idx >> 11;              // / 2048
    int j = idx & (PACKED - 1);

    int v = wp[idx] & 255;
    float s = scales[o * NBLK + (j >> 5)];
    float w0 = cent[(v >> 4) & 15] * s;   // element k0 = 2j
    float w1 = cent[v & 15] * s;          // element k0+1

    uint32_t t0, t1;
    asm("cvt.rna.tf32.f32 %0, %1;" : "=r"(t0) : "f"(w0));
    asm("cvt.rna.tf32.f32 %0, %1;" : "=r"(t1) : "f"(w1));

    int k0 = 2 * j;
    int ntile = o >> 7;             // / BN
    int np = o & 127;
    int kt = k0 >> 5;
    int kp = k0 & 31;
    int kk = kp >> 3;
    int q  = kp & 7;
    int c  = q & 3;                 // even (0 or 2)
    int hi = q >> 2;
    int nf = np >> 3;
    int lane = (np & 7) * 4 + c;

    float* tile = g_Bt + (size_t)ntile * (NKT * TILE_FLOATS) + (size_t)kt * TILE_FLOATS;
    int f0 = (kk * 16 + nf) * 64 + lane * 2 + hi;
    tile[f0]     = __uint_as_float(t0);
    tile[f0 + 2] = __uint_as_float(t1);   // c+1 -> lane+1 -> +2 floats
}

// ---------------------------------------------------------------------------
// Pre-pass 2: tf32-round X -> fragment-ordered g_At.
// ---------------------------------------------------------------------------
__global__ void retile_x_kernel(const float* __restrict__ X, int M) {
    int t = blockIdx.x * blockDim.x + threadIdx.x;
    if (t >= M * (IN_F / 4)) return;
    int e = t * 4;
    int m = e >> 12;
    int i = e & (IN_F - 1);

    float4 v = *reinterpret_cast<const float4*>(X + (size_t)m * IN_F + i);
    uint32_t t0, t1, t2, t3;
    asm("cvt.rna.tf32.f32 %0, %1;" : "=r"(t0) : "f"(v.x));
    asm("cvt.rna.tf32.f32 %0, %1;" : "=r"(t1) : "f"(v.y));
    asm("cvt.rna.tf32.f32 %0, %1;" : "=r"(t2) : "f"(v.z));
    asm("cvt.rna.tf32.f32 %0, %1;" : "=r"(t3) : "f"(v.w));

    int mtile = m >> 7;
    int mp = m & 127;
    int mf = mp >> 4;
    int rr = mp & 15;
    int kt = i >> 5;
    int kp = i & 31;
    int kk = kp >> 3;
    int hi = (kp & 7) >> 2;
    int lane0 = (rr & 7) * 4;
    int slot = ((rr >> 3) & 1) + 2 * hi;

    float* tile = g_At + (size_t)mtile * (NKT * TILE_FLOATS) + (size_t)kt * TILE_FLOATS;
    int base = (kk * 8 + mf) * 128 + lane0 * 4 + slot;
    tile[base]      = __uint_as_float(t0);
    tile[base + 4]  = __uint_as_float(t1);
    tile[base + 8]  = __uint_as_float(t2);
    tile[base + 12] = __uint_as_float(t3);
}

// ---------------------------------------------------------------------------
// GEMM: 128x128x32 tiles, 4 warps (2x2, warp tile 64x64), mma.sync tf32,
// 2 CTA/SM. Fragment-ordered SMEM + register double-buffered fragments
// (prefetch kk+1 group while mma'ing group kk).
// ---------------------------------------------------------------------------
__device__ __forceinline__ void mma_tf32(float* c, const uint32_t* a, const uint32_t* b) {
    asm volatile(
        "mma.sync.aligned.m16n8k8.row.col.f32.tf32.tf32.f32 "
        "{%0,%1,%2,%3}, {%4,%5,%6,%7}, {%8,%9}, {%0,%1,%2,%3};\n"
        : "+f"(c[0]), "+f"(c[1]), "+f"(c[2]), "+f"(c[3])
        : "r"(a[0]), "r"(a[1]), "r"(a[2]), "r"(a[3]),
          "r"(b[0]), "r"(b[1]));
}

__device__ __forceinline__ void load_frags(uint32_t a[4][4], uint32_t b[8][2],
                                           const float* A0, const float* B0,
                                           int kk, int wm, int wn, int lane) {
#pragma unroll
    for (int ma = 0; ma < 4; ma++) {
        const float4 v = *reinterpret_cast<const float4*>(
            A0 + (kk * 8 + wm * 4 + ma) * 128 + lane * 4);
        a[ma][0] = __float_as_uint(v.x);
        a[ma][1] = __float_as_uint(v.y);
        a[ma][2] = __float_as_uint(v.z);
        a[ma][3] = __float_as_uint(v.w);
    }
#pragma unroll
    for (int nb = 0; nb < 8; nb++) {
        const float2 v = *reinterpret_cast<const float2*>(
            B0 + (kk * 16 + wn * 8 + nb) * 64 + lane * 2);
        b[nb][0] = __float_as_uint(v.x);
        b[nb][1] = __float_as_uint(v.y);
    }
}

__device__ __forceinline__ void load_stage(uint32_t sbase, const float* Asrc,
                                           const float* Bsrc, int kt, int buf, int tid) {
    uint32_t d = sbase + (uint32_t)buf * STAGE_BYTES + (uint32_t)tid * 16;
    const float* pa = Asrc + (size_t)kt * TILE_FLOATS + tid * 4;
    const float* pb = Bsrc + (size_t)kt * TILE_FLOATS + tid * 4;
#pragma unroll
    for (int i = 0; i < 8; i++) {
        asm volatile("cp.async.cg.shared.global [%0], [%1], 16;\n"
                     :: "r"(d + i * 2048), "l"(pa + i * 512));
        asm volatile("cp.async.cg.shared.global [%0], [%1], 16;\n"
                     :: "r"(d + 16384 + i * 2048), "l"(pb + i * 512));
    }
}

__global__ void __launch_bounds__(128, 2)
gemm_tf32_kernel(float* __restrict__ Out) {
    extern __shared__ float smem[];

    const int tid  = threadIdx.x;
    const int warp = tid >> 5;
    const int lane = tid & 31;
    const int wm = warp >> 1;              // 0..1 -> M offset wm*64
    const int wn = warp & 1;               // 0..1 -> N offset wn*64

    const float* Ag = g_At + (size_t)blockIdx.y * (NKT * TILE_FLOATS);
    const float* Bg = g_Bt + (size_t)blockIdx.x * (NKT * TILE_FLOATS);

    const uint32_t sbase = (uint32_t)__cvta_generic_to_shared(smem);

    float c[4][8][4];
#pragma unroll
    for (int i = 0; i < 4; i++)
#pragma unroll
        for (int j = 0; j < 8; j++)
#pragma unroll
            for (int k = 0; k < 4; k++) c[i][j][k] = 0.0f;

    load_stage(sbase, Ag, Bg, 0, 0, tid);
    asm volatile("cp.async.commit_group;\n" ::: "memory");
    load_stage(sbase, Ag, Bg, 1, 1, tid);
    asm volatile("cp.async.commit_group;\n" ::: "memory");

    uint32_t a[2][4][4];
    uint32_t b[2][8][2];

    for (int kt = 0; kt < NKT; kt++) {
        asm volatile("cp.async.wait_group 1;\n" ::: "memory");   // my tile-kt copies done
        __syncthreads();                                         // everyone's visible; old buf free

        const float* S  = smem + (size_t)(kt % STAGES) * (STAGE_BYTES / 4);
        const float* A0 = S;
        const float* B0 = S + TILE_FLOATS;

        // prefetch fragment group 0 first (critical path), then bulk-issue
        // the next stage's cp.asyncs under the LDS latency.
        load_frags(a[0], b[0], A0, B0, 0, wm, wn, lane);

        if (kt + 2 < NKT)
            load_stage(sbase, Ag, Bg, kt + 2, (kt + 2) % STAGES, tid);
        asm volatile("cp.async.commit_group;\n" ::: "memory");

#pragma unroll
        for (int kk = 0; kk < 4; kk++) {
            const int cur = kk & 1;
            if (kk < 3)
                load_frags(a[cur ^ 1], b[cur ^ 1], A0, B0, kk + 1, wm, wn, lane);
#pragma unroll
            for (int ma = 0; ma < 4; ma++)
#pragma unroll
                for (int nb = 0; nb < 8; nb++)
                    mma_tf32(c[ma][nb], a[cur][ma], b[cur][nb]);
        }
    }

    // epilogue
    float* Og = Out + (size_t)blockIdx.y * BM * OUT_F + blockIdx.x * BN;
#pragma unroll
    for (int ma = 0; ma < 4; ma++) {
#pragma unroll
        for (int nb = 0; nb < 8; nb++) {
            int r  = wm * 64 + ma * 16 + (lane >> 2);
            int cc = wn * 64 + nb * 8 + 2 * (lane & 3);
            *reinterpret_cast<float2*>(&Og[(size_t)r * OUT_F + cc]) =
                make_float2(c[ma][nb][0], c[ma][nb][1]);
            *reinterpret_cast<float2*>(&Og[(size_t)(r + 8) * OUT_F + cc]) =
                make_float2(c[ma][nb][2], c[ma][nb][3]);
        }
    }
}

// ---------------------------------------------------------------------------
extern "C" void kernel_launch(void* const* d_in, const int* in_sizes, int n_in,
                              void* d_out, int out_size) {
    const float* x      = (const float*)d_in[0];   // [M, 4096] fp32
    const int*   wp     = (const int*)d_in[1];     // [4096, 2048] int32 bytes
    const float* cent   = (const float*)d_in[2];   // [16]
    const float* scales = (const float*)d_in[3];   // [4096, 64]
    float* out = (float*)d_out;

    const int M = in_sizes[0] / IN_F;              // 8192

    int totalW = OUT_F * PACKED;
    dequant_kernel<<<(totalW + 255) / 256, 256>>>(wp, cent, scales);

    int totalX4 = M * (IN_F / 4);
    retile_x_kernel<<<(totalX4 + 255) / 256, 256>>>(x, M);

    cudaFuncSetAttribute(gemm_tf32_kernel,
                         cudaFuncAttributeMaxDynamicSharedMemorySize, SMEM_BYTES);
    dim3 grid(OUT_F / BN, M / BM);                 // (32, 64)
    gemm_tf32_kernel<<<grid, 128, SMEM_BYTES>>>(out);
}